// round 3
// baseline (speedup 1.0000x reference)
#include <cuda_runtime.h>
#include <math.h>

// ---------------------------------------------------------------------------
// Model constants
// ---------------------------------------------------------------------------
#define B_   4
#define S_   4096
#define D_   768
#define H_   12
#define DH_  64
#define BS_  64
#define L_   2
#define FF_  3072
#define NB_  64
#define R_   3
#define NSEL_ 8
#define NT_  (B_ * S_)          // 16384 tokens

// ---------------------------------------------------------------------------
// Scratch (no cudaMalloc allowed — __device__ globals)
// ---------------------------------------------------------------------------
__device__ float g_h[NT_ * D_];          // hidden state     [16384, 768]
__device__ float g_qkv[NT_ * 3 * D_];    // qkv              [16384, 2304]
__device__ float g_attn[NT_ * D_];       // attention output [16384, 768]
__device__ float g_ff[NT_ * FF_];        // ff1 activations  [16384, 3072]
__device__ float g_tmp[NT_ * D_];        // gemm epilogue tmp[16384, 768]
__device__ float g_pooled[B_ * D_];      // pooler output

// ---------------------------------------------------------------------------
// Block reduction helper (256 threads)
// ---------------------------------------------------------------------------
__device__ __forceinline__ float block_reduce_sum(float v, float* shared8) {
    int lane = threadIdx.x & 31, warp = threadIdx.x >> 5;
#pragma unroll
    for (int o = 16; o > 0; o >>= 1) v += __shfl_xor_sync(0xffffffffu, v, o);
    if (lane == 0) shared8[warp] = v;
    __syncthreads();
    if (warp == 0) {
        float w = (lane < 8) ? shared8[lane] : 0.f;
#pragma unroll
        for (int o = 4; o > 0; o >>= 1) w += __shfl_xor_sync(0xffffffffu, w, o);
        if (lane == 0) shared8[0] = w;
    }
    __syncthreads();
    float r = shared8[0];
    __syncthreads();   // allow reuse of shared8
    return r;
}

// ---------------------------------------------------------------------------
// Embedding + LayerNorm:  h = LN(emb[ids] + pos_emb)
// ---------------------------------------------------------------------------
__global__ void __launch_bounds__(256) embed_ln_kernel(
    const int* __restrict__ ids, const float* __restrict__ emb,
    const float* __restrict__ pos, const float* __restrict__ gw,
    const float* __restrict__ bw, float* __restrict__ out)
{
    int t = blockIdx.x;
    int s = t & (S_ - 1);
    size_t id = (size_t)ids[t];
    __shared__ float buf[D_];
    __shared__ float red[8];

    float lsum = 0.f;
    for (int j = threadIdx.x; j < D_; j += 256) {
        float v = emb[id * D_ + j] + pos[(size_t)s * D_ + j];
        buf[j] = v;
        lsum += v;
    }
    float mean = block_reduce_sum(lsum, red) * (1.f / D_);
    float lv = 0.f;
    for (int j = threadIdx.x; j < D_; j += 256) {
        float d = buf[j] - mean;
        lv += d * d;
    }
    float var = block_reduce_sum(lv, red) * (1.f / D_);
    float inv = rsqrtf(var + 1e-12f);
    float* orow = out + (size_t)t * D_;
    for (int j = threadIdx.x; j < D_; j += 256)
        orow[j] = (buf[j] - mean) * inv * gw[j] + bw[j];
}

// ---------------------------------------------------------------------------
// Residual add + LayerNorm (in place on h):  h = LN(h + x)
// ---------------------------------------------------------------------------
__global__ void __launch_bounds__(256) add_ln_kernel(
    float* __restrict__ h, const float* __restrict__ x,
    const float* __restrict__ gw, const float* __restrict__ bw)
{
    int t = blockIdx.x;
    __shared__ float buf[D_];
    __shared__ float red[8];
    const float* hr = h + (size_t)t * D_;
    const float* xr = x + (size_t)t * D_;

    float lsum = 0.f;
    for (int j = threadIdx.x; j < D_; j += 256) {
        float v = hr[j] + xr[j];
        buf[j] = v;
        lsum += v;
    }
    float mean = block_reduce_sum(lsum, red) * (1.f / D_);
    float lv = 0.f;
    for (int j = threadIdx.x; j < D_; j += 256) {
        float d = buf[j] - mean;
        lv += d * d;
    }
    float var = block_reduce_sum(lv, red) * (1.f / D_);
    float inv = rsqrtf(var + 1e-12f);
    float* orow = h + (size_t)t * D_;
    for (int j = threadIdx.x; j < D_; j += 256)
        orow[j] = (buf[j] - mean) * inv * gw[j] + bw[j];
}

// ---------------------------------------------------------------------------
// SGEMM:  C[M,N] = A[M,K] @ B[K,N] + bias  (optional GELU)
// BM=BN=128, BK=16, 256 threads, 8x8 per thread. M,N,K all multiples ok here.
// ---------------------------------------------------------------------------
__device__ __forceinline__ float gelu_f(float x) {
    float x3 = x * x * x;
    return 0.5f * x * (1.f + tanhf(0.7978845608028654f * (x + 0.044715f * x3)));
}

template <int ACT>
__global__ void __launch_bounds__(256) sgemm_kernel(
    const float* __restrict__ A, const float* __restrict__ B,
    const float* __restrict__ bias, float* __restrict__ C,
    int M, int N, int K)
{
    const int BK = 16;
    __shared__ float As[BK][128];   // transposed A tile
    __shared__ float Bs[BK][128];

    int tid = threadIdx.x;
    int block_row = blockIdx.y * 128;
    int block_col = blockIdx.x * 128;

    int a_row = tid >> 2;          // 0..63 (and +64)
    int a_col = (tid & 3) * 4;     // 0,4,8,12
    int b_row = tid >> 5;          // 0..7 (and +8)
    int b_col = (tid & 31) * 4;    // 0..124

    int ty = tid >> 4;             // 0..15
    int tx = tid & 15;             // 0..15

    float acc[8][8];
#pragma unroll
    for (int i = 0; i < 8; i++)
#pragma unroll
        for (int j = 0; j < 8; j++) acc[i][j] = 0.f;

    float ar[8], br[8];

    for (int k0 = 0; k0 < K; k0 += BK) {
#pragma unroll
        for (int s = 0; s < 2; s++) {
            int r = a_row + s * 64;
            float4 v = *(const float4*)(A + (size_t)(block_row + r) * K + k0 + a_col);
            As[a_col + 0][r] = v.x;
            As[a_col + 1][r] = v.y;
            As[a_col + 2][r] = v.z;
            As[a_col + 3][r] = v.w;
        }
#pragma unroll
        for (int s = 0; s < 2; s++) {
            int r = b_row + s * 8;
            *(float4*)(&Bs[r][b_col]) =
                *(const float4*)(B + (size_t)(k0 + r) * N + block_col + b_col);
        }
        __syncthreads();

#pragma unroll
        for (int k = 0; k < BK; k++) {
            *(float4*)(ar)     = *(const float4*)(&As[k][ty * 8]);
            *(float4*)(ar + 4) = *(const float4*)(&As[k][ty * 8 + 4]);
            *(float4*)(br)     = *(const float4*)(&Bs[k][tx * 8]);
            *(float4*)(br + 4) = *(const float4*)(&Bs[k][tx * 8 + 4]);
#pragma unroll
            for (int i = 0; i < 8; i++)
#pragma unroll
                for (int j = 0; j < 8; j++)
                    acc[i][j] += ar[i] * br[j];
        }
        __syncthreads();
    }

#pragma unroll
    for (int i = 0; i < 8; i++) {
        int row = block_row + ty * 8 + i;
#pragma unroll
        for (int j = 0; j < 8; j += 4) {
            int col = block_col + tx * 8 + j;
            float4 o;
            o.x = acc[i][j + 0] + bias[col + 0];
            o.y = acc[i][j + 1] + bias[col + 1];
            o.z = acc[i][j + 2] + bias[col + 2];
            o.w = acc[i][j + 3] + bias[col + 3];
            if (ACT == 1) {
                o.x = gelu_f(o.x); o.y = gelu_f(o.y);
                o.z = gelu_f(o.z); o.w = gelu_f(o.w);
            }
            *(float4*)(C + (size_t)row * N + col) = o;
        }
    }
}

// ---------------------------------------------------------------------------
// Sparse block attention.
// Grid: (NB, H, B). 256 threads. Full 64x512 score tile in padded smem.
// q_s[64][65], kv_s[64][65], sc[64][513] -> 164608 B dynamic smem.
// ---------------------------------------------------------------------------
#define ATTN_SMEM ((2 * 64 * 65 + 64 * 513) * (int)sizeof(float))

__global__ void __launch_bounds__(256) attn_kernel(
    const float* __restrict__ qkv, const int* __restrict__ rand_idx,
    const int* __restrict__ mask, float* __restrict__ out)
{
    int qb = blockIdx.x, hd = blockIdx.y, b = blockIdx.z;
    extern __shared__ float sm[];
    float* q_s  = sm;                 // [64][65]
    float* kv_s = sm + 64 * 65;       // [64][65]
    float* sc   = sm + 2 * 64 * 65;   // [64][513]
    __shared__ float bias_s[64];
    __shared__ int sel[NSEL_];

    int tid = threadIdx.x;
    if (tid < NSEL_) {
        int s;
        switch (tid) {
            case 0: s = 0; break;
            case 1: s = (qb + NB_ - 1) & (NB_ - 1); break;
            case 2: s = qb; break;
            case 3: s = (qb + 1) & (NB_ - 1); break;
            case 4: s = NB_ - 1; break;
            default: s = rand_idx[qb * R_ + (tid - 5)]; break;
        }
        sel[tid] = s;
    }

    const float scale = 0.125f;  // 1/sqrt(64)
    size_t qbase = ((size_t)(b * S_ + qb * BS_)) * (3 * D_) + hd * DH_;
    for (int idx = tid; idx < 64 * 64; idx += 256) {
        int i = idx >> 6, d = idx & 63;
        q_s[i * 65 + d] = qkv[qbase + (size_t)i * (3 * D_) + d] * scale;
    }
    __syncthreads();

    int i_ = tid >> 2;        // query row 0..63
    int jg = tid & 3;         // column group

    // --- scores: sc[i][kb*64 + j] = q.k * scale + bias -----------------
    for (int kb = 0; kb < NSEL_; kb++) {
        int sb = sel[kb];
        size_t kbase = ((size_t)(b * S_ + sb * BS_)) * (3 * D_) + D_ + hd * DH_;
        for (int idx = tid; idx < 64 * 64; idx += 256) {
            int j = idx >> 6, d = idx & 63;
            kv_s[j * 65 + d] = qkv[kbase + (size_t)j * (3 * D_) + d];
        }
        if (tid < 64)
            bias_s[tid] = (mask[b * S_ + sb * BS_ + tid] > 0) ? 0.f : -1e9f;
        __syncthreads();

        float accj[16];
#pragma unroll
        for (int jj = 0; jj < 16; jj++) accj[jj] = 0.f;

#pragma unroll
        for (int d0 = 0; d0 < 64; d0 += 8) {
            float qr[8];
#pragma unroll
            for (int d = 0; d < 8; d++) qr[d] = q_s[i_ * 65 + d0 + d];
#pragma unroll
            for (int jj = 0; jj < 16; jj++) {
                int j = jg * 16 + jj;
                float a = 0.f;
#pragma unroll
                for (int d = 0; d < 8; d++)
                    a += qr[d] * kv_s[j * 65 + d0 + d];
                accj[jj] += a;
            }
        }
#pragma unroll
        for (int jj = 0; jj < 16; jj++) {
            int j = jg * 16 + jj;
            sc[i_ * 513 + kb * 64 + j] = accj[jj] + bias_s[j];
        }
        __syncthreads();
    }

    // --- softmax over 512 keys per row (8 warps, 8 rows each) ----------
    int warp = tid >> 5, lane = tid & 31;
    for (int r = warp; r < 64; r += 8) {
        float mx = -1e30f;
        for (int c = lane; c < 512; c += 32) mx = fmaxf(mx, sc[r * 513 + c]);
#pragma unroll
        for (int o = 16; o > 0; o >>= 1) mx = fmaxf(mx, __shfl_xor_sync(0xffffffffu, mx, o));
        float sum = 0.f;
        for (int c = lane; c < 512; c += 32) {
            float e = __expf(sc[r * 513 + c] - mx);
            sc[r * 513 + c] = e;
            sum += e;
        }
#pragma unroll
        for (int o = 16; o > 0; o >>= 1) sum += __shfl_xor_sync(0xffffffffu, sum, o);
        float inv = 1.f / sum;
        for (int c = lane; c < 512; c += 32) sc[r * 513 + c] *= inv;
    }
    __syncthreads();

    // --- out = attn @ V -------------------------------------------------
    float o_acc[16];
#pragma unroll
    for (int r = 0; r < 16; r++) o_acc[r] = 0.f;
    int c0 = jg * 16;

    for (int kb = 0; kb < NSEL_; kb++) {
        int sb = sel[kb];
        size_t vbase = ((size_t)(b * S_ + sb * BS_)) * (3 * D_) + 2 * D_ + hd * DH_;
        for (int idx = tid; idx < 64 * 64; idx += 256) {
            int j = idx >> 6, d = idx & 63;
            kv_s[j * 65 + d] = qkv[vbase + (size_t)j * (3 * D_) + d];
        }
        __syncthreads();
#pragma unroll 8
        for (int k = 0; k < 64; k++) {
            float a = sc[i_ * 513 + kb * 64 + k];
#pragma unroll
            for (int r = 0; r < 16; r++)
                o_acc[r] += a * kv_s[k * 65 + c0 + r];
        }
        __syncthreads();
    }

    size_t obase = ((size_t)(b * S_ + qb * BS_ + i_)) * D_ + hd * DH_ + c0;
#pragma unroll
    for (int r = 0; r < 16; r += 4)
        *(float4*)(out + obase + r) =
            make_float4(o_acc[r], o_acc[r + 1], o_acc[r + 2], o_acc[r + 3]);
}

// ---------------------------------------------------------------------------
// Pooler: pooled[b] = tanh(h[b,0,:] @ Wp + bp)
// ---------------------------------------------------------------------------
__global__ void __launch_bounds__(256) pooler_kernel(
    const float* __restrict__ h, const float* __restrict__ Wp,
    const float* __restrict__ bp, float* __restrict__ pooled)
{
    int b = blockIdx.x;
    __shared__ float hrow[D_];
    for (int j = threadIdx.x; j < D_; j += 256)
        hrow[j] = h[(size_t)b * S_ * D_ + j];
    __syncthreads();
    for (int j = threadIdx.x; j < D_; j += 256) {
        float acc = bp[j];
        for (int k = 0; k < D_; k++)
            acc += hrow[k] * Wp[(size_t)k * D_ + j];
        pooled[b * D_ + j] = tanhf(acc);
    }
}

// ---------------------------------------------------------------------------
// Classifier + double softmax + loss. One block, 8 warps = 8 logits.
// ---------------------------------------------------------------------------
__global__ void __launch_bounds__(256) cls_kernel(
    const float* __restrict__ pooled, const float* __restrict__ Wc,
    const float* __restrict__ bc, const int* __restrict__ label,
    float* __restrict__ out, int out_size)
{
    __shared__ float logits[8];
    int warp = threadIdx.x >> 5, lane = threadIdx.x & 31;
    {
        int b = warp >> 1, c = warp & 1;
        float acc = 0.f;
        for (int k = lane; k < D_; k += 32)
            acc += pooled[b * D_ + k] * Wc[k * 2 + c];
#pragma unroll
        for (int o = 16; o > 0; o >>= 1) acc += __shfl_xor_sync(0xffffffffu, acc, o);
        if (lane == 0) logits[warp] = acc + bc[c];
    }
    __syncthreads();
    if (threadIdx.x == 0) {
        float loss = 0.f;
        for (int b = 0; b < B_; b++) {
            float l0 = logits[b * 2], l1 = logits[b * 2 + 1];
            float m = fmaxf(l0, l1);
            float e0 = expf(l0 - m), e1 = expf(l1 - m);
            float s = e0 + e1;
            float p0 = e0 / s, p1 = e1 / s;
            out[b * 2 + 0] = p0;
            out[b * 2 + 1] = p1;
            // faithful to reference: log_softmax applied to the softmax output
            float pm = fmaxf(p0, p1);
            float q0 = expf(p0 - pm), q1 = expf(p1 - pm);
            float lse = pm + logf(q0 + q1);
            float lp = (label[b] == 0 ? p0 : p1) - lse;
            loss -= lp;
        }
        loss *= (1.f / B_);
        if (out_size > 8) out[8] = loss;
    }
}

// ---------------------------------------------------------------------------
// Launch
// ---------------------------------------------------------------------------
extern "C" void kernel_launch(void* const* d_in, const int* in_sizes, int n_in,
                              void* d_out, int out_size)
{
    const int*   input_ids = (const int*)d_in[0];
    const int*   attn_mask = (const int*)d_in[1];
    const int*   label     = (const int*)d_in[2];
    const int*   rand_idx  = (const int*)d_in[3];
    const float* emb   = (const float*)d_in[4];
    const float* pos   = (const float*)d_in[5];
    const float* ln_eg = (const float*)d_in[6];
    const float* ln_eb = (const float*)d_in[7];
    const float* Wqkv  = (const float*)d_in[8];
    const float* bqkv  = (const float*)d_in[9];
    const float* Wo    = (const float*)d_in[10];
    const float* bo    = (const float*)d_in[11];
    const float* ln1g  = (const float*)d_in[12];
    const float* ln1b  = (const float*)d_in[13];
    const float* Wff1  = (const float*)d_in[14];
    const float* bff1  = (const float*)d_in[15];
    const float* Wff2  = (const float*)d_in[16];
    const float* bff2  = (const float*)d_in[17];
    const float* ln2g  = (const float*)d_in[18];
    const float* ln2b  = (const float*)d_in[19];
    const float* Wp    = (const float*)d_in[20];
    const float* bp    = (const float*)d_in[21];
    const float* Wc    = (const float*)d_in[22];
    const float* bc    = (const float*)d_in[23];

    float *h, *qkv, *attn, *ff, *tmp, *pooled;
    cudaGetSymbolAddress((void**)&h,      g_h);
    cudaGetSymbolAddress((void**)&qkv,    g_qkv);
    cudaGetSymbolAddress((void**)&attn,   g_attn);
    cudaGetSymbolAddress((void**)&ff,     g_ff);
    cudaGetSymbolAddress((void**)&tmp,    g_tmp);
    cudaGetSymbolAddress((void**)&pooled, g_pooled);

    cudaFuncSetAttribute(attn_kernel,
                         cudaFuncAttributeMaxDynamicSharedMemorySize, ATTN_SMEM);

    embed_ln_kernel<<<NT_, 256>>>(input_ids, emb, pos, ln_eg, ln_eb, h);

    for (int l = 0; l < L_; l++) {
        // qkv = h @ Wqkv[l] + bqkv[l]
        sgemm_kernel<0><<<dim3((3 * D_) / 128, NT_ / 128), 256>>>(
            h, Wqkv + (size_t)l * D_ * 3 * D_, bqkv + (size_t)l * 3 * D_,
            qkv, NT_, 3 * D_, D_);

        // sparse attention
        attn_kernel<<<dim3(NB_, H_, B_), 256, ATTN_SMEM>>>(
            qkv, rand_idx, attn_mask, attn);

        // o-proj
        sgemm_kernel<0><<<dim3(D_ / 128, NT_ / 128), 256>>>(
            attn, Wo + (size_t)l * D_ * D_, bo + (size_t)l * D_,
            tmp, NT_, D_, D_);
        add_ln_kernel<<<NT_, 256>>>(h, tmp, ln1g + (size_t)l * D_, ln1b + (size_t)l * D_);

        // ff1 (+gelu)
        sgemm_kernel<1><<<dim3(FF_ / 128, NT_ / 128), 256>>>(
            h, Wff1 + (size_t)l * D_ * FF_, bff1 + (size_t)l * FF_,
            ff, NT_, FF_, D_);
        // ff2
        sgemm_kernel<0><<<dim3(D_ / 128, NT_ / 128), 256>>>(
            ff, Wff2 + (size_t)l * FF_ * D_, bff2 + (size_t)l * D_,
            tmp, NT_, D_, FF_);
        add_ln_kernel<<<NT_, 256>>>(h, tmp, ln2g + (size_t)l * D_, ln2b + (size_t)l * D_);
    }

    pooler_kernel<<<B_, 256>>>(h, Wp, bp, pooled);
    cls_kernel<<<1, 256>>>(pooled, Wc, bc, label, (float*)d_out, out_size);
}